// round 3
// baseline (speedup 1.0000x reference)
#include <cuda_runtime.h>
#include <cuda_bf16.h>
#include <math.h>

// Problem constants
#define NN 50000
#define EE 800000
#define IND 128
#define HID 64
#define NH 8
#define OUTD 64
#define FEATW (NH * HID)   // 512

// ---------------- scratch (static device globals; no allocation) -------------
__device__ float g_feat[(size_t)NN * FEATW];   // [N, H*F] projected features
__device__ float g_el[NN * NH];
__device__ float g_er[NN * NH];
__device__ float g_x[NN * HID];                // inter-layer activations [N,64]
__device__ float g_bsum[3 * HID];              // per-layer sum_h bias[h][f]
__device__ int   g_deg[NN];
__device__ int   g_fill[NN];
__device__ int   g_rowptr[NN + 1];
__device__ int   g_col[EE];                    // src node per CSR slot

// ---------------- CSR build --------------------------------------------------
__global__ void zero2_kernel(int* a, int* b, int n) {
    int i = blockIdx.x * blockDim.x + threadIdx.x;
    if (i < n) { a[i] = 0; b[i] = 0; }
}

__global__ void hist_kernel(const int* __restrict__ dst, int* __restrict__ deg, int e) {
    int i = blockIdx.x * blockDim.x + threadIdx.x;
    if (i < e) atomicAdd(&deg[dst[i]], 1);
}

__global__ void scan_kernel(const int* __restrict__ deg, int* __restrict__ rowptr,
                            int n, int total) {
    __shared__ int part[1024];
    int t = threadIdx.x;
    int chunk = (n + 1023) / 1024;
    int s0 = t * chunk;
    int s1 = min(s0 + chunk, n);
    int s = 0;
    for (int i = s0; i < s1; i++) s += deg[i];
    part[t] = s;
    __syncthreads();
    for (int off = 1; off < 1024; off <<= 1) {
        int v = (t >= off) ? part[t - off] : 0;
        __syncthreads();
        part[t] += v;
        __syncthreads();
    }
    int run = (t == 0) ? 0 : part[t - 1];
    for (int i = s0; i < s1; i++) { rowptr[i] = run; run += deg[i]; }
    if (t == 1023) rowptr[n] = total;
}

__global__ void scatter_kernel(const int* __restrict__ src, const int* __restrict__ dst,
                               const int* __restrict__ rowptr, int* __restrict__ fill,
                               int* __restrict__ col, int e) {
    int i = blockIdx.x * blockDim.x + threadIdx.x;
    if (i < e) {
        int d = dst[i];
        int pos = rowptr[d] + atomicAdd(&fill[d], 1);
        col[pos] = src[i];
    }
}

// ---------------- bias head-sum ---------------------------------------------
__global__ void bsum_kernel(const float* __restrict__ b1, const float* __restrict__ b2,
                            const float* __restrict__ b3, float* __restrict__ bsum) {
    int t = threadIdx.x;            // 192 threads
    int l = t >> 6, f = t & 63;
    const float* b = (l == 0) ? b1 : ((l == 1) ? b2 : b3);
    float s = 0.f;
#pragma unroll
    for (int h = 0; h < NH; h++) s += b[h * HID + f];
    bsum[t] = s;
}

// ---------------- SGEMM: C[m][n] = sum_k A[m][k]*B[n][k] (+bias[n]) ----------
// BM=BN=64, BK=32, 256 threads, 4x4 per thread.
__global__ __launch_bounds__(256) void gemm_nt(
    const float* __restrict__ A, const float* __restrict__ B,
    float* __restrict__ C, const float* __restrict__ bias,
    int M, int N, int K)
{
    __shared__ float As[32][68];
    __shared__ float Bs[32][68];
    int tid = threadIdx.x;
    int tx = tid & 15, ty = tid >> 4;
    int m0 = blockIdx.x * 64, n0 = blockIdx.y * 64;
    int lr = tid >> 3;          // 0..31
    int lc = (tid & 7) * 4;     // 0..28
    float acc[4][4] = {};

    for (int k0 = 0; k0 < K; k0 += 32) {
#pragma unroll
        for (int rr = 0; rr < 2; rr++) {
            int row = m0 + lr + rr * 32;
            float4 v = make_float4(0.f, 0.f, 0.f, 0.f);
            if (row < M) v = *(const float4*)(A + (size_t)row * K + k0 + lc);
            As[lc + 0][lr + rr * 32] = v.x;
            As[lc + 1][lr + rr * 32] = v.y;
            As[lc + 2][lr + rr * 32] = v.z;
            As[lc + 3][lr + rr * 32] = v.w;
            int brow = n0 + lr + rr * 32;   // N is a multiple of 64
            float4 w = *(const float4*)(B + (size_t)brow * K + k0 + lc);
            Bs[lc + 0][lr + rr * 32] = w.x;
            Bs[lc + 1][lr + rr * 32] = w.y;
            Bs[lc + 2][lr + rr * 32] = w.z;
            Bs[lc + 3][lr + rr * 32] = w.w;
        }
        __syncthreads();
#pragma unroll
        for (int kk = 0; kk < 32; kk++) {
            float4 a = *(const float4*)&As[kk][ty * 4];
            float4 b = *(const float4*)&Bs[kk][tx * 4];
            float av[4] = {a.x, a.y, a.z, a.w};
            float bv[4] = {b.x, b.y, b.z, b.w};
#pragma unroll
            for (int i = 0; i < 4; i++)
#pragma unroll
                for (int j = 0; j < 4; j++)
                    acc[i][j] += av[i] * bv[j];
        }
        __syncthreads();
    }
#pragma unroll
    for (int i = 0; i < 4; i++) {
        int row = m0 + ty * 4 + i;
        if (row < M) {
#pragma unroll
            for (int j = 0; j < 4; j++) {
                int c = n0 + tx * 4 + j;
                float v = acc[i][j];
                if (bias) v += bias[c];
                C[(size_t)row * N + c] = v;
            }
        }
    }
}

// ---------------- el/er: per-node per-head attention logits ------------------
__global__ __launch_bounds__(256) void elr_kernel(
    const float* __restrict__ feat, const float* __restrict__ al,
    const float* __restrict__ ar, float* __restrict__ el, float* __restrict__ er, int n)
{
    int w = (blockIdx.x * blockDim.x + threadIdx.x) >> 5;
    int lane = threadIdx.x & 31;
    if (w >= n) return;
    const float* fr = feat + (size_t)w * FEATW;
#pragma unroll
    for (int h = 0; h < NH; h++) {
        float v1 = fr[h * 64 + lane];
        float v2 = fr[h * 64 + 32 + lane];
        float sl = v1 * al[h * 64 + lane] + v2 * al[h * 64 + 32 + lane];
        float sr = v1 * ar[h * 64 + lane] + v2 * ar[h * 64 + 32 + lane];
#pragma unroll
        for (int o = 16; o; o >>= 1) {
            sl += __shfl_xor_sync(0xffffffffu, sl, o);
            sr += __shfl_xor_sync(0xffffffffu, sr, o);
        }
        if (lane == 0) { el[w * 8 + h] = sl; er[w * 8 + h] = sr; }
    }
}

// ---------------- warp-per-dst aggregation w/ online edge-softmax ------------
// Register layout: acc[q] (float4), q=0..3, lane l: covers feat floats
// [4*(q*32+l) .. +3]; head = 2q + (l>>4); f (within head) = 4*(l&15)..+3.
__global__ __launch_bounds__(256) void aggregate_kernel(
    const float* __restrict__ feat, const float* __restrict__ el,
    const float* __restrict__ er, const int* __restrict__ rowptr,
    const int* __restrict__ colv, const float* __restrict__ bsum,
    float* __restrict__ xout, int n)
{
    int d = (blockIdx.x * blockDim.x + threadIdx.x) >> 5;
    int lane = threadIdx.x & 31;
    if (d >= n) return;

    float erh = (lane < 8) ? er[d * 8 + lane] : 0.f;
    float mh = -1e30f, sh = 0.f;
    float4 acc[4];
#pragma unroll
    for (int q = 0; q < 4; q++) acc[q] = make_float4(0.f, 0.f, 0.f, 0.f);

    int jb = rowptr[d], je = rowptr[d + 1];
    for (int j = jb; j < je; j++) {
        int s = colv[j];
        float p = 0.f, scale = 1.f;
        if (lane < 8) {
            float e = el[s * 8 + lane] + erh;
            e = (e > 0.f) ? e : 0.2f * e;           // leaky 0.2 on edge logit
            float mn = fmaxf(mh, e);
            scale = __expf(mh - mn);
            p = __expf(e - mn);
            sh = sh * scale + p;
            mh = mn;
        }
        const float4* f4 = (const float4*)(feat + (size_t)s * FEATW);
#pragma unroll
        for (int q = 0; q < 4; q++) {
            int h = q * 2 + (lane >> 4);
            float sc = __shfl_sync(0xffffffffu, scale, h);
            float pp = __shfl_sync(0xffffffffu, p, h);
            float4 v = f4[q * 32 + lane];
            acc[q].x = acc[q].x * sc + pp * v.x;
            acc[q].y = acc[q].y * sc + pp * v.y;
            acc[q].z = acc[q].z * sc + pp * v.z;
            acc[q].w = acc[q].w * sc + pp * v.w;
        }
    }

    // divide by softmax denom (per head); empty dst => 0 contribution
    float inv = 0.f;
    if (lane < 8) inv = (sh > 0.f) ? (1.f / sh) : 0.f;
#pragma unroll
    for (int q = 0; q < 4; q++) {
        int h = q * 2 + (lane >> 4);
        float iv = __shfl_sync(0xffffffffu, inv, h);
        acc[q].x *= iv; acc[q].y *= iv; acc[q].z *= iv; acc[q].w *= iv;
    }

    // head-sum: sum the 4 regs (heads {0,2,4,6} or {1,3,5,7}), then xor-16.
    float4 r = acc[0];
    r.x += acc[1].x + acc[2].x + acc[3].x;
    r.y += acc[1].y + acc[2].y + acc[3].y;
    r.z += acc[1].z + acc[2].z + acc[3].z;
    r.w += acc[1].w + acc[2].w + acc[3].w;
    r.x += __shfl_xor_sync(0xffffffffu, r.x, 16);
    r.y += __shfl_xor_sync(0xffffffffu, r.y, 16);
    r.z += __shfl_xor_sync(0xffffffffu, r.z, 16);
    r.w += __shfl_xor_sync(0xffffffffu, r.w, 16);

    if (lane < 16) {
        int f = lane * 4;
        float4 bb = *(const float4*)(bsum + f);
        float4 o;
        o.x = r.x + bb.x; o.x = (o.x > 0.f) ? o.x : 0.01f * o.x;
        o.y = r.y + bb.y; o.y = (o.y > 0.f) ? o.y : 0.01f * o.y;
        o.z = r.z + bb.z; o.z = (o.z > 0.f) ? o.z : 0.01f * o.z;
        o.w = r.w + bb.w; o.w = (o.w > 0.f) ? o.w : 0.01f * o.w;
        *(float4*)(xout + (size_t)d * HID + f) = o;
    }
}

// ---------------- launch -----------------------------------------------------
extern "C" void kernel_launch(void* const* d_in, const int* in_sizes, int n_in,
                              void* d_out, int out_size)
{
    const float* inputs = (const float*)d_in[0];
    const int*   src    = (const int*)d_in[1];
    const int*   dst    = (const int*)d_in[2];
    const float* W1  = (const float*)d_in[3];
    const float* al1 = (const float*)d_in[4];
    const float* ar1 = (const float*)d_in[5];
    const float* b1  = (const float*)d_in[6];
    const float* W2  = (const float*)d_in[7];
    const float* al2 = (const float*)d_in[8];
    const float* ar2 = (const float*)d_in[9];
    const float* b2  = (const float*)d_in[10];
    const float* W3  = (const float*)d_in[11];
    const float* al3 = (const float*)d_in[12];
    const float* ar3 = (const float*)d_in[13];
    const float* b3  = (const float*)d_in[14];
    const float* Wm  = (const float*)d_in[15];
    const float* bm  = (const float*)d_in[16];
    float* out = (float*)d_out;

    float *feat, *el, *er, *xb, *bsum;
    int *deg, *fill, *rowptr, *col;
    cudaGetSymbolAddress((void**)&feat,   g_feat);
    cudaGetSymbolAddress((void**)&el,     g_el);
    cudaGetSymbolAddress((void**)&er,     g_er);
    cudaGetSymbolAddress((void**)&xb,     g_x);
    cudaGetSymbolAddress((void**)&bsum,   g_bsum);
    cudaGetSymbolAddress((void**)&deg,    g_deg);
    cudaGetSymbolAddress((void**)&fill,   g_fill);
    cudaGetSymbolAddress((void**)&rowptr, g_rowptr);
    cudaGetSymbolAddress((void**)&col,    g_col);

    const int nB = (NN + 255) / 256;
    const int eB = (EE + 255) / 256;
    const int wB = (NN * 32 + 255) / 256;       // warp-per-node grids
    const int mT = (NN + 63) / 64;              // GEMM M tiles

    // CSR build (re-done every call: deterministic work, graph-capturable)
    zero2_kernel<<<nB, 256>>>(deg, fill, NN);
    hist_kernel<<<eB, 256>>>(dst, deg, EE);
    scan_kernel<<<1, 1024>>>(deg, rowptr, NN, EE);
    scatter_kernel<<<eB, 256>>>(src, dst, rowptr, fill, col, EE);
    bsum_kernel<<<1, 192>>>(b1, b2, b3, bsum);

    // layer 1
    gemm_nt<<<dim3(mT, FEATW / 64), 256>>>(inputs, W1, feat, nullptr, NN, FEATW, IND);
    elr_kernel<<<wB, 256>>>(feat, al1, ar1, el, er, NN);
    aggregate_kernel<<<wB, 256>>>(feat, el, er, rowptr, col, bsum + 0, xb, NN);

    // layer 2
    gemm_nt<<<dim3(mT, FEATW / 64), 256>>>(xb, W2, feat, nullptr, NN, FEATW, HID);
    elr_kernel<<<wB, 256>>>(feat, al2, ar2, el, er, NN);
    aggregate_kernel<<<wB, 256>>>(feat, el, er, rowptr, col, bsum + 64, xb, NN);

    // layer 3
    gemm_nt<<<dim3(mT, FEATW / 64), 256>>>(xb, W3, feat, nullptr, NN, FEATW, HID);
    elr_kernel<<<wB, 256>>>(feat, al3, ar3, el, er, NN);
    aggregate_kernel<<<wB, 256>>>(feat, el, er, rowptr, col, bsum + 128, xb, NN);

    // final projection + bias
    gemm_nt<<<dim3(mT, OUTD / 64), 256>>>(xb, Wm, out, bm, NN, OUTD, HID);
}

// round 13
// speedup vs baseline: 1.0860x; 1.0860x over previous
#include <cuda_runtime.h>
#include <cuda_bf16.h>
#include <math.h>

// Problem constants
#define NN 50000
#define EE 800000
#define IND 128
#define HID 64
#define NH 8
#define OUTD 64
#define FEATW (NH * HID)   // 512

// ---------------- scratch (static device globals; no allocation) -------------
__device__ float g_feat[(size_t)NN * FEATW];   // [N, H*F] projected features
__device__ float g_el[NN * NH];
__device__ float g_er[NN * NH];
__device__ float g_x[NN * HID];                // inter-layer activations [N,64]
__device__ float g_bsum[3 * HID];              // per-layer sum_h bias[h][f]
__device__ int   g_deg[NN];
__device__ int   g_fill[NN];
__device__ int   g_rowptr[NN + 1];
__device__ int   g_col[EE];                    // src node per CSR slot

// ---------------- CSR build --------------------------------------------------
__global__ void zero2_kernel(int* a, int* b, int n) {
    int i = blockIdx.x * blockDim.x + threadIdx.x;
    if (i < n) { a[i] = 0; b[i] = 0; }
}

__global__ void hist_kernel(const int* __restrict__ dst, int* __restrict__ deg, int e) {
    int i = blockIdx.x * blockDim.x + threadIdx.x;
    if (i < e) atomicAdd(&deg[dst[i]], 1);
}

__global__ void scan_kernel(const int* __restrict__ deg, int* __restrict__ rowptr,
                            int n, int total) {
    __shared__ int part[1024];
    int t = threadIdx.x;
    int chunk = (n + 1023) / 1024;
    int s0 = t * chunk;
    int s1 = min(s0 + chunk, n);
    int s = 0;
    for (int i = s0; i < s1; i++) s += deg[i];
    part[t] = s;
    __syncthreads();
    for (int off = 1; off < 1024; off <<= 1) {
        int v = (t >= off) ? part[t - off] : 0;
        __syncthreads();
        part[t] += v;
        __syncthreads();
    }
    int run = (t == 0) ? 0 : part[t - 1];
    for (int i = s0; i < s1; i++) { rowptr[i] = run; run += deg[i]; }
    if (t == 1023) rowptr[n] = total;
}

__global__ void scatter_kernel(const int* __restrict__ src, const int* __restrict__ dst,
                               const int* __restrict__ rowptr, int* __restrict__ fill,
                               int* __restrict__ col, int e) {
    int i = blockIdx.x * blockDim.x + threadIdx.x;
    if (i < e) {
        int d = dst[i];
        int pos = rowptr[d] + atomicAdd(&fill[d], 1);
        col[pos] = src[i];
    }
}

// ---------------- bias head-sum ---------------------------------------------
__global__ void bsum_kernel(const float* __restrict__ b1, const float* __restrict__ b2,
                            const float* __restrict__ b3, float* __restrict__ bsum) {
    int t = threadIdx.x;            // 192 threads
    int l = t >> 6, f = t & 63;
    const float* b = (l == 0) ? b1 : ((l == 1) ? b2 : b3);
    float s = 0.f;
#pragma unroll
    for (int h = 0; h < NH; h++) s += b[h * HID + f];
    bsum[t] = s;
}

// ---------------- SGEMM (f32x2 FFMA2): C[m][n] = sum_k A[m][k]*B[n][k] -------
// BM=BN=64, BK=32, 256 threads, 4x4 per thread via packed f32x2.
// A is stored in smem DUPLICATED ((a,a) pairs) so the FFMA2 broadcast operand
// is a single ld.shared.b64; B pairs come packed from LDS.128.
// Optional fused epilogues: bias add (final layer) and el/er attention logits
// (feat layers, where each 64-col N-tile == one head).
__global__ __launch_bounds__(256) void gemm_nt(
    const float* __restrict__ A, const float* __restrict__ B,
    float* __restrict__ C, const float* __restrict__ bias,
    const float* __restrict__ al, const float* __restrict__ ar,
    float* __restrict__ el, float* __restrict__ er,
    int M, int N, int K)
{
    __shared__ float As2[32][132];   // duplicated pairs: [k][2m],[k][2m+1]
    __shared__ float Bs[32][68];
    int tid = threadIdx.x;
    int tx = tid & 15, ty = tid >> 4;
    int m0 = blockIdx.x * 64, n0 = blockIdx.y * 64;
    int lr = tid >> 3;          // 0..31
    int lc = (tid & 7) * 4;     // 0..28

    unsigned long long acc2[4][2] = {};   // (c[i][0],c[i][1]), (c[i][2],c[i][3])

    for (int k0 = 0; k0 < K; k0 += 32) {
#pragma unroll
        for (int rr = 0; rr < 2; rr++) {
            int mloc = lr + rr * 32;
            int row = m0 + mloc;
            float4 v = make_float4(0.f, 0.f, 0.f, 0.f);
            if (row < M) v = *(const float4*)(A + (size_t)row * K + k0 + lc);
            *(float2*)&As2[lc + 0][2 * mloc] = make_float2(v.x, v.x);
            *(float2*)&As2[lc + 1][2 * mloc] = make_float2(v.y, v.y);
            *(float2*)&As2[lc + 2][2 * mloc] = make_float2(v.z, v.z);
            *(float2*)&As2[lc + 3][2 * mloc] = make_float2(v.w, v.w);
            int brow = n0 + mloc;       // N is a multiple of 64
            float4 w = *(const float4*)(B + (size_t)brow * K + k0 + lc);
            Bs[lc + 0][mloc] = w.x;
            Bs[lc + 1][mloc] = w.y;
            Bs[lc + 2][mloc] = w.z;
            Bs[lc + 3][mloc] = w.w;
        }
        __syncthreads();
#pragma unroll
        for (int kk = 0; kk < 32; kk++) {
            ulonglong2 bq = *(const ulonglong2*)&Bs[kk][tx * 4];
#pragma unroll
            for (int i = 0; i < 4; i++) {
                unsigned long long ad =
                    *(const unsigned long long*)&As2[kk][2 * (ty * 4 + i)];
                asm("fma.rn.f32x2 %0, %1, %2, %0;"
                    : "+l"(acc2[i][0]) : "l"(ad), "l"(bq.x));
                asm("fma.rn.f32x2 %0, %1, %2, %0;"
                    : "+l"(acc2[i][1]) : "l"(ad), "l"(bq.y));
            }
        }
        __syncthreads();
    }

    // unpack to scalars
    float cf[4][4];
#pragma unroll
    for (int i = 0; i < 4; i++) {
        unsigned int u0, u1, u2, u3;
        asm("mov.b64 {%0, %1}, %2;" : "=r"(u0), "=r"(u1) : "l"(acc2[i][0]));
        asm("mov.b64 {%0, %1}, %2;" : "=r"(u2), "=r"(u3) : "l"(acc2[i][1]));
        cf[i][0] = __uint_as_float(u0);
        cf[i][1] = __uint_as_float(u1);
        cf[i][2] = __uint_as_float(u2);
        cf[i][3] = __uint_as_float(u3);
    }

    // store C (+ optional bias)
#pragma unroll
    for (int i = 0; i < 4; i++) {
        int row = m0 + ty * 4 + i;
        if (row < M) {
#pragma unroll
            for (int j = 0; j < 4; j++) {
                int c = n0 + tx * 4 + j;
                float v = cf[i][j];
                if (bias) v += bias[c];
                C[(size_t)row * N + c] = v;
            }
        }
    }

    // fused el/er: this N-tile is exactly head h = blockIdx.y (feat layers)
    if (al) {
        int h = blockIdx.y;
        float4 av = *(const float4*)(al + h * 64 + tx * 4);
        float4 rv = *(const float4*)(ar + h * 64 + tx * 4);
#pragma unroll
        for (int i = 0; i < 4; i++) {
            float pl = cf[i][0] * av.x + cf[i][1] * av.y + cf[i][2] * av.z + cf[i][3] * av.w;
            float pr = cf[i][0] * rv.x + cf[i][1] * rv.y + cf[i][2] * rv.z + cf[i][3] * rv.w;
#pragma unroll
            for (int o = 1; o < 16; o <<= 1) {
                pl += __shfl_xor_sync(0xffffffffu, pl, o);
                pr += __shfl_xor_sync(0xffffffffu, pr, o);
            }
            int row = m0 + ty * 4 + i;
            if ((tid & 15) == 0 && row < M) {
                el[row * 8 + h] = pl;
                er[row * 8 + h] = pr;
            }
        }
    }
}

// ---------------- warp-per-dst aggregation w/ online edge-softmax ------------
// Register layout: acc[q] (float4), q=0..3, lane l: covers feat floats
// [4*(q*32+l) .. +3]; head = 2q + (l>>4). Edge loop unrolled x2 with all
// gathers (colv, el, feat rows) issued ahead of the serial exp chain.
__global__ __launch_bounds__(256) void aggregate_kernel(
    const float* __restrict__ feat, const float* __restrict__ el,
    const float* __restrict__ er, const int* __restrict__ rowptr,
    const int* __restrict__ colv, const float* __restrict__ bsum,
    float* __restrict__ xout, int n)
{
    int d = (blockIdx.x * blockDim.x + threadIdx.x) >> 5;
    int lane = threadIdx.x & 31;
    if (d >= n) return;

    float erh = (lane < 8) ? er[d * 8 + lane] : 0.f;
    float mh = -1e30f, sh = 0.f;
    float4 acc[4];
#pragma unroll
    for (int q = 0; q < 4; q++) acc[q] = make_float4(0.f, 0.f, 0.f, 0.f);

    int jb = rowptr[d], je = rowptr[d + 1];
    int j = jb;
    for (; j + 2 <= je; j += 2) {
        int s0 = colv[j], s1 = colv[j + 1];
        float q0 = 0.f, q1 = 0.f;
        if (lane < 8) {
            q0 = el[s0 * 8 + lane];
            q1 = el[s1 * 8 + lane];
        }
        const float4* f40 = (const float4*)(feat + (size_t)s0 * FEATW);
        const float4* f41 = (const float4*)(feat + (size_t)s1 * FEATW);
        float4 v0[4], v1[4];
#pragma unroll
        for (int q = 0; q < 4; q++) {
            v0[q] = f40[q * 32 + lane];
            v1[q] = f41[q * 32 + lane];
        }
        float p0 = 0.f, sc0 = 1.f, p1 = 0.f, sc1 = 1.f;
        if (lane < 8) {
            float e = q0 + erh;
            e = (e > 0.f) ? e : 0.2f * e;
            float mn = fmaxf(mh, e);
            sc0 = __expf(mh - mn);
            p0 = __expf(e - mn);
            sh = sh * sc0 + p0;
            mh = mn;
            e = q1 + erh;
            e = (e > 0.f) ? e : 0.2f * e;
            mn = fmaxf(mh, e);
            sc1 = __expf(mh - mn);
            p1 = __expf(e - mn);
            sh = sh * sc1 + p1;
            mh = mn;
        }
#pragma unroll
        for (int q = 0; q < 4; q++) {
            int h = q * 2 + (lane >> 4);
            float sc = __shfl_sync(0xffffffffu, sc0, h);
            float pp = __shfl_sync(0xffffffffu, p0, h);
            acc[q].x = acc[q].x * sc + pp * v0[q].x;
            acc[q].y = acc[q].y * sc + pp * v0[q].y;
            acc[q].z = acc[q].z * sc + pp * v0[q].z;
            acc[q].w = acc[q].w * sc + pp * v0[q].w;
            sc = __shfl_sync(0xffffffffu, sc1, h);
            pp = __shfl_sync(0xffffffffu, p1, h);
            acc[q].x = acc[q].x * sc + pp * v1[q].x;
            acc[q].y = acc[q].y * sc + pp * v1[q].y;
            acc[q].z = acc[q].z * sc + pp * v1[q].z;
            acc[q].w = acc[q].w * sc + pp * v1[q].w;
        }
    }
    if (j < je) {  // remainder edge
        int s = colv[j];
        float p = 0.f, scale = 1.f;
        if (lane < 8) {
            float e = el[s * 8 + lane] + erh;
            e = (e > 0.f) ? e : 0.2f * e;
            float mn = fmaxf(mh, e);
            scale = __expf(mh - mn);
            p = __expf(e - mn);
            sh = sh * scale + p;
            mh = mn;
        }
        const float4* f4 = (const float4*)(feat + (size_t)s * FEATW);
#pragma unroll
        for (int q = 0; q < 4; q++) {
            int h = q * 2 + (lane >> 4);
            float sc = __shfl_sync(0xffffffffu, scale, h);
            float pp = __shfl_sync(0xffffffffu, p, h);
            float4 v = f4[q * 32 + lane];
            acc[q].x = acc[q].x * sc + pp * v.x;
            acc[q].y = acc[q].y * sc + pp * v.y;
            acc[q].z = acc[q].z * sc + pp * v.z;
            acc[q].w = acc[q].w * sc + pp * v.w;
        }
    }

    // divide by softmax denom (per head); empty dst => 0 contribution
    float inv = 0.f;
    if (lane < 8) inv = (sh > 0.f) ? (1.f / sh) : 0.f;
#pragma unroll
    for (int q = 0; q < 4; q++) {
        int h = q * 2 + (lane >> 4);
        float iv = __shfl_sync(0xffffffffu, inv, h);
        acc[q].x *= iv; acc[q].y *= iv; acc[q].z *= iv; acc[q].w *= iv;
    }

    // head-sum: sum the 4 regs (heads {0,2,4,6} or {1,3,5,7}), then xor-16.
    float4 r = acc[0];
    r.x += acc[1].x + acc[2].x + acc[3].x;
    r.y += acc[1].y + acc[2].y + acc[3].y;
    r.z += acc[1].z + acc[2].z + acc[3].z;
    r.w += acc[1].w + acc[2].w + acc[3].w;
    r.x += __shfl_xor_sync(0xffffffffu, r.x, 16);
    r.y += __shfl_xor_sync(0xffffffffu, r.y, 16);
    r.z += __shfl_xor_sync(0xffffffffu, r.z, 16);
    r.w += __shfl_xor_sync(0xffffffffu, r.w, 16);

    if (lane < 16) {
        int f = lane * 4;
        float4 bb = *(const float4*)(bsum + f);
        float4 o;
        o.x = r.x + bb.x; o.x = (o.x > 0.f) ? o.x : 0.01f * o.x;
        o.y = r.y + bb.y; o.y = (o.y > 0.f) ? o.y : 0.01f * o.y;
        o.z = r.z + bb.z; o.z = (o.z > 0.f) ? o.z : 0.01f * o.z;
        o.w = r.w + bb.w; o.w = (o.w > 0.f) ? o.w : 0.01f * o.w;
        *(float4*)(xout + (size_t)d * HID + f) = o;
    }
}

// ---------------- launch -----------------------------------------------------
extern "C" void kernel_launch(void* const* d_in, const int* in_sizes, int n_in,
                              void* d_out, int out_size)
{
    const float* inputs = (const float*)d_in[0];
    const int*   src    = (const int*)d_in[1];
    const int*   dst    = (const int*)d_in[2];
    const float* W1  = (const float*)d_in[3];
    const float* al1 = (const float*)d_in[4];
    const float* ar1 = (const float*)d_in[5];
    const float* b1  = (const float*)d_in[6];
    const float* W2  = (const float*)d_in[7];
    const float* al2 = (const float*)d_in[8];
    const float* ar2 = (const float*)d_in[9];
    const float* b2  = (const float*)d_in[10];
    const float* W3  = (const float*)d_in[11];
    const float* al3 = (const float*)d_in[12];
    const float* ar3 = (const float*)d_in[13];
    const float* b3  = (const float*)d_in[14];
    const float* Wm  = (const float*)d_in[15];
    const float* bm  = (const float*)d_in[16];
    float* out = (float*)d_out;

    float *feat, *el, *er, *xb, *bsum;
    int *deg, *fill, *rowptr, *col;
    cudaGetSymbolAddress((void**)&feat,   g_feat);
    cudaGetSymbolAddress((void**)&el,     g_el);
    cudaGetSymbolAddress((void**)&er,     g_er);
    cudaGetSymbolAddress((void**)&xb,     g_x);
    cudaGetSymbolAddress((void**)&bsum,   g_bsum);
    cudaGetSymbolAddress((void**)&deg,    g_deg);
    cudaGetSymbolAddress((void**)&fill,   g_fill);
    cudaGetSymbolAddress((void**)&rowptr, g_rowptr);
    cudaGetSymbolAddress((void**)&col,    g_col);

    const int nB = (NN + 255) / 256;
    const int eB = (EE + 255) / 256;
    const int wB = (NN * 32 + 255) / 256;       // warp-per-node grids
    const int mT = (NN + 63) / 64;              // GEMM M tiles

    // CSR build (re-done every call: deterministic work, graph-capturable)
    zero2_kernel<<<nB, 256>>>(deg, fill, NN);
    hist_kernel<<<eB, 256>>>(dst, deg, EE);
    scan_kernel<<<1, 1024>>>(deg, rowptr, NN, EE);
    scatter_kernel<<<eB, 256>>>(src, dst, rowptr, fill, col, EE);
    bsum_kernel<<<1, 192>>>(b1, b2, b3, bsum);

    // layer 1 (GEMM with fused el/er epilogue)
    gemm_nt<<<dim3(mT, FEATW / 64), 256>>>(inputs, W1, feat, nullptr,
                                           al1, ar1, el, er, NN, FEATW, IND);
    aggregate_kernel<<<wB, 256>>>(feat, el, er, rowptr, col, bsum + 0, xb, NN);

    // layer 2
    gemm_nt<<<dim3(mT, FEATW / 64), 256>>>(xb, W2, feat, nullptr,
                                           al2, ar2, el, er, NN, FEATW, HID);
    aggregate_kernel<<<wB, 256>>>(feat, el, er, rowptr, col, bsum + 64, xb, NN);

    // layer 3
    gemm_nt<<<dim3(mT, FEATW / 64), 256>>>(xb, W3, feat, nullptr,
                                           al3, ar3, el, er, NN, FEATW, HID);
    aggregate_kernel<<<wB, 256>>>(feat, el, er, rowptr, col, bsum + 128, xb, NN);

    // final projection + bias
    gemm_nt<<<dim3(mT, OUTD / 64), 256>>>(xb, Wm, out, bm,
                                          nullptr, nullptr, nullptr, nullptr,
                                          NN, OUTD, HID);
}